// round 2
// baseline (speedup 1.0000x reference)
#include <cuda_runtime.h>

#define NN 50000
#define EE 800000
#define DD 128

// ---- device scratch (no allocs allowed) ----
__device__ float g_agg[NN * DD];
__device__ float g_h1[NN * DD];
__device__ float g_h2[NN * DD];
__device__ int   g_cnt[NN];
__device__ int   g_pos[NN];
__device__ int   g_row[NN + 1];
__device__ float g_inv[NN];
__device__ int   g_srcl[EE];
__device__ int   g_is64;

// ---------------- edge dtype detection ----------------
// JAX with x64 disabled canonicalizes int64 -> int32. Detect which layout the
// harness actually gave us: for little-endian int64 values in [0, 50000), every
// odd 32-bit word is 0. For int32 data, odd words are random node ids.
__global__ void k_detect(const int* __restrict__ eiw) {
    if (threadIdx.x == 0 && blockIdx.x == 0) {
        int is64 = 1;
        for (int i = 1; i < 2048; i += 2)
            if (eiw[i] != 0) { is64 = 0; break; }
        g_is64 = is64;
    }
}

__device__ __forceinline__ int edge_at(const int* __restrict__ eiw, int idx) {
    return g_is64 ? eiw[2 * idx] : eiw[idx];
}

// ---------------- CSR build ----------------
__global__ void k_zero_cnt() {
    int i = blockIdx.x * blockDim.x + threadIdx.x;
    if (i < NN) g_cnt[i] = 0;
}

__global__ void k_count(const int* __restrict__ eiw) {
    int e = blockIdx.x * blockDim.x + threadIdx.x;
    if (e < EE) {
        int d = edge_at(eiw, EE + e);
        atomicAdd(&g_cnt[d], 1);
    }
}

// single-block scan over 50000 counts; also writes g_pos, g_inv, g_row
__global__ void k_scan() {
    __shared__ int sm[1024];
    int t = threadIdx.x;
    const int CH = (NN + 1023) / 1024;  // 49
    int lo = t * CH;
    int hi = lo + CH; if (hi > NN) hi = NN;
    int s = 0;
    for (int i = lo; i < hi; ++i) s += g_cnt[i];
    sm[t] = s;
    __syncthreads();
    // inclusive Hillis-Steele scan
    for (int off = 1; off < 1024; off <<= 1) {
        int tmp = (t >= off) ? sm[t - off] : 0;
        __syncthreads();
        sm[t] += tmp;
        __syncthreads();
    }
    int run = sm[t] - s;  // exclusive prefix for this thread's chunk
    for (int i = lo; i < hi; ++i) {
        g_row[i] = run;
        g_pos[i] = run;
        int c = g_cnt[i];
        g_inv[i] = 1.0f / (float)(c > 0 ? c : 1);
        run += c;
    }
    if (t == 1023) g_row[NN] = sm[1023];
}

__global__ void k_fill(const int* __restrict__ eiw) {
    int e = blockIdx.x * blockDim.x + threadIdx.x;
    if (e < EE) {
        int d = edge_at(eiw, EE + e);
        int p = atomicAdd(&g_pos[d], 1);
        g_srcl[p] = edge_at(eiw, e);
    }
}

// ---------------- mean aggregation: one warp per node ----------------
// sel: 0 = hext, 1 = g_h1, 2 = g_h2
__global__ void k_aggregate(const float* __restrict__ hext, int sel) {
    const float* h = (sel == 1) ? (const float*)g_h1
                   : (sel == 2) ? (const float*)g_h2 : hext;
    int w = (blockIdx.x * blockDim.x + threadIdx.x) >> 5;
    int lane = threadIdx.x & 31;
    if (w >= NN) return;
    int s = g_row[w], e = g_row[w + 1];
    float4 acc = make_float4(0.f, 0.f, 0.f, 0.f);
    for (int i = s; i < e; ++i) {
        int src = g_srcl[i];
        float4 v = *(const float4*)(h + (size_t)src * DD + lane * 4);
        acc.x += v.x; acc.y += v.y; acc.z += v.z; acc.w += v.w;
    }
    float iv = g_inv[w];
    float4 r = make_float4(acc.x * iv, acc.y * iv, acc.z * iv, acc.w * iv);
    *(float4*)(g_agg + (size_t)w * DD + lane * 4) = r;
}

// ---------------- fused SAGE GEMM ----------------
// out[n][o] = relu?( sum_k g_agg[n][k]*Wl[o][k] + sum_k Aself[n][k]*Wr[o][k] + b[o] )
// 64-node x 128-out tile, 256 threads, 4x8 register blocking, K tiled by 16.
__global__ void __launch_bounds__(256) k_gemm(
    const float* __restrict__ aself_ext, int asel,
    const float* __restrict__ Wl, const float* __restrict__ Wr,
    const float* __restrict__ bias,
    float* out_ext, int osel, int do_relu)
{
    const float* Aself = (asel == 1) ? (const float*)g_h1
                       : (asel == 2) ? (const float*)g_h2 : aself_ext;
    float* out = (osel == 1) ? (float*)g_h1
               : (osel == 2) ? (float*)g_h2 : out_ext;

    __shared__ float Ws[16 * 128];      // Ws[kk][o]
    __shared__ float As[64 * 16];       // As[r][kk]

    int t = threadIdx.x;
    int n0 = blockIdx.x * 64;
    int tr = t >> 4, tc = t & 15;
    int r0 = tr * 4, c0 = tc * 8;

    float acc[4][8];
#pragma unroll
    for (int i = 0; i < 4; i++)
#pragma unroll
        for (int j = 0; j < 8; j++) acc[i][j] = 0.f;

#pragma unroll
    for (int phase = 0; phase < 2; ++phase) {
        const float* A = phase ? Aself : (const float*)g_agg;
        const float* W = phase ? Wr : Wl;
        const float4* A4 = (const float4*)A;
        const float4* W4 = (const float4*)W;
        for (int k0 = 0; k0 < 128; k0 += 16) {
            // load W tile transposed: Ws[kk][o] = W[o][k0+kk]
#pragma unroll
            for (int rep = 0; rep < 2; ++rep) {
                int idx = rep * 256 + t;            // 0..511
                int o = idx >> 2, q = idx & 3;
                float4 v = W4[o * 32 + (k0 >> 2) + q];
                int kk = q * 4;
                Ws[(kk + 0) * 128 + o] = v.x;
                Ws[(kk + 1) * 128 + o] = v.y;
                Ws[(kk + 2) * 128 + o] = v.z;
                Ws[(kk + 3) * 128 + o] = v.w;
            }
            // load A tile: As[r][kk]
            {
                int r = t >> 2, q = t & 3;
                int n = n0 + r;
                float4 v = make_float4(0.f, 0.f, 0.f, 0.f);
                if (n < NN) v = A4[(size_t)n * 32 + (k0 >> 2) + q];
                *(float4*)&As[r * 16 + q * 4] = v;
            }
            __syncthreads();
#pragma unroll
            for (int kk = 0; kk < 16; ++kk) {
                float av[4];
                av[0] = As[(r0 + 0) * 16 + kk];
                av[1] = As[(r0 + 1) * 16 + kk];
                av[2] = As[(r0 + 2) * 16 + kk];
                av[3] = As[(r0 + 3) * 16 + kk];
                float4 w0 = *(float4*)&Ws[kk * 128 + c0];
                float4 w1 = *(float4*)&Ws[kk * 128 + c0 + 4];
                float wv[8] = { w0.x, w0.y, w0.z, w0.w, w1.x, w1.y, w1.z, w1.w };
#pragma unroll
                for (int i = 0; i < 4; i++)
#pragma unroll
                    for (int j = 0; j < 8; j++)
                        acc[i][j] += av[i] * wv[j];
            }
            __syncthreads();
        }
    }

    float bv[8];
#pragma unroll
    for (int j = 0; j < 8; j++) bv[j] = bias[c0 + j];
#pragma unroll
    for (int i = 0; i < 4; i++) {
        int n = n0 + r0 + i;
        if (n < NN) {
#pragma unroll
            for (int j = 0; j < 8; j++) {
                float v = acc[i][j] + bv[j];
                if (do_relu) v = fmaxf(v, 0.f);
                acc[i][j] = v;
            }
            *(float4*)(out + (size_t)n * DD + c0) =
                make_float4(acc[i][0], acc[i][1], acc[i][2], acc[i][3]);
            *(float4*)(out + (size_t)n * DD + c0 + 4) =
                make_float4(acc[i][4], acc[i][5], acc[i][6], acc[i][7]);
        }
    }
}

// ---------------- decoder: one warp per node ----------------
__global__ void k_decoder(const float* __restrict__ h3, const float* __restrict__ Wo,
                          const float* __restrict__ bo, float* __restrict__ out2) {
    int w = (blockIdx.x * blockDim.x + threadIdx.x) >> 5;
    int lane = threadIdx.x & 31;
    if (w >= NN) return;
    float4 h  = *(const float4*)(h3 + (size_t)w * DD + lane * 4);
    float4 w0 = *(const float4*)(Wo + lane * 4);
    float4 w1 = *(const float4*)(Wo + DD + lane * 4);
    float p0 = h.x * w0.x + h.y * w0.y + h.z * w0.z + h.w * w0.w;
    float p1 = h.x * w1.x + h.y * w1.y + h.z * w1.z + h.w * w1.w;
    for (int off = 16; off; off >>= 1) {
        p0 += __shfl_xor_sync(0xffffffffu, p0, off);
        p1 += __shfl_xor_sync(0xffffffffu, p1, off);
    }
    if (lane == 0) {
        out2[w * 2 + 0] = p0 + bo[0];
        out2[w * 2 + 1] = p1 + bo[1];
    }
}

extern "C" void kernel_launch(void* const* d_in, const int* in_sizes, int n_in,
                              void* d_out, int out_size) {
    const float* x   = (const float*)d_in[0];
    const int*   eiw = (const int*)d_in[1];   // edge_index as 32-bit words (dtype auto-detected)
    const float* Wl1 = (const float*)d_in[2];
    const float* Wr1 = (const float*)d_in[3];
    const float* b1  = (const float*)d_in[4];
    const float* Wl2 = (const float*)d_in[5];
    const float* Wr2 = (const float*)d_in[6];
    const float* b2  = (const float*)d_in[7];
    const float* Wl3 = (const float*)d_in[8];
    const float* Wr3 = (const float*)d_in[9];
    const float* b3  = (const float*)d_in[10];
    const float* Wo  = (const float*)d_in[11];
    const float* bo  = (const float*)d_in[12];

    float* out  = (float*)d_out;
    float* out2 = out;              // [N, 2]
    float* h3   = out + NN * 2;     // [N, 128]

    // CSR build (edges identical across layers)
    k_detect<<<1, 32>>>(eiw);
    k_zero_cnt<<<(NN + 255) / 256, 256>>>();
    k_count<<<(EE + 255) / 256, 256>>>(eiw);
    k_scan<<<1, 1024>>>();
    k_fill<<<(EE + 255) / 256, 256>>>(eiw);

    int gemm_blocks = (NN + 63) / 64;
    int warp_blocks = (NN + 7) / 8;

    // layer 1: x -> g_h1 (relu)
    k_aggregate<<<warp_blocks, 256>>>(x, 0);
    k_gemm<<<gemm_blocks, 256>>>(x, 0, Wl1, Wr1, b1, nullptr, 1, 1);

    // layer 2: g_h1 -> g_h2 (relu)
    k_aggregate<<<warp_blocks, 256>>>(nullptr, 1);
    k_gemm<<<gemm_blocks, 256>>>(nullptr, 1, Wl2, Wr2, b2, nullptr, 2, 1);

    // layer 3: g_h2 -> h3 (no relu), written straight into d_out
    k_aggregate<<<warp_blocks, 256>>>(nullptr, 2);
    k_gemm<<<gemm_blocks, 256>>>(nullptr, 2, Wl3, Wr3, b3, h3, 0, 0);

    // decoder
    k_decoder<<<warp_blocks, 256>>>(h3, Wo, bo, out2);
}

// round 3
// speedup vs baseline: 1.3731x; 1.3731x over previous
#include <cuda_runtime.h>

#define NN 50000
#define EE 800000
#define DD 128
#define NB 49   // scan blocks: ceil(50000/1024)

// ---- device scratch (no allocs allowed) ----
__device__ float g_agg[NN * DD];
__device__ float g_h1[NN * DD];
__device__ float g_h2[NN * DD];
__device__ int   g_cnt[NN];
__device__ int   g_pos[NN];
__device__ int   g_row[NN + 1];
__device__ float g_inv[NN];
__device__ int   g_srcl[EE];
__device__ int   g_is64;
__device__ int   g_bsum[64];
__device__ int   g_boff[64];

// ---------------- edge dtype detection (warp-parallel) ----------------
// JAX x64-disabled canonicalizes int64 -> int32. For little-endian int64
// values in [0, 50000) every odd 32-bit word is 0; for int32 data odd words
// are random node ids.
__global__ void k_detect(const int* __restrict__ eiw) {
    int t = threadIdx.x;
    int bad = 0;
    for (int i = 2 * t + 1; i < 4096; i += 64)
        if (eiw[i] != 0) bad = 1;
    unsigned m = __ballot_sync(0xffffffffu, bad);
    if (t == 0) g_is64 = (m == 0);
}

__device__ __forceinline__ int edge_at(const int* __restrict__ eiw, int idx) {
    return g_is64 ? eiw[2 * idx] : eiw[idx];
}

// ---------------- CSR build ----------------
__global__ void k_zero_cnt() {
    int i = blockIdx.x * blockDim.x + threadIdx.x;
    if (i < NN) g_cnt[i] = 0;
}

__global__ void k_count(const int* __restrict__ eiw) {
    int e = blockIdx.x * blockDim.x + threadIdx.x;
    if (e < EE) {
        int d = edge_at(eiw, EE + e);
        atomicAdd(&g_cnt[d], 1);
    }
}

// ---- hierarchical exclusive scan over g_cnt: 3 tiny kernels ----
// s1: per-block (1024 elems) local exclusive scan into g_row, block total -> g_bsum
__global__ void __launch_bounds__(1024) k_scan1() {
    int b = blockIdx.x, t = threadIdx.x;
    int i = b * 1024 + t;
    int v = (i < NN) ? g_cnt[i] : 0;
    int lane = t & 31, w = t >> 5;
    // inclusive warp scan
    int x = v;
#pragma unroll
    for (int o = 1; o < 32; o <<= 1) {
        int y = __shfl_up_sync(0xffffffffu, x, o);
        if (lane >= o) x += y;
    }
    __shared__ int ws[32];
    if (lane == 31) ws[w] = x;
    __syncthreads();
    if (w == 0) {
        int y = ws[lane];
#pragma unroll
        for (int o = 1; o < 32; o <<= 1) {
            int z = __shfl_up_sync(0xffffffffu, y, o);
            if (lane >= o) y += z;
        }
        ws[lane] = y;
    }
    __syncthreads();
    int incl = x + (w > 0 ? ws[w - 1] : 0);
    if (i < NN) g_row[i] = incl - v;           // block-local exclusive
    if (t == 1023) g_bsum[b] = incl;           // block total
}

// s2: one warp scans the 49 block sums -> exclusive g_boff; writes g_row[NN]
__global__ void k_scan2() {
    int lane = threadIdx.x;
    int v0 = (lane < NB) ? g_bsum[lane] : 0;
    int v1 = (32 + lane < NB) ? g_bsum[32 + lane] : 0;
    int x0 = v0, x1 = v1;
#pragma unroll
    for (int o = 1; o < 32; o <<= 1) {
        int y = __shfl_up_sync(0xffffffffu, x0, o);
        if (lane >= o) x0 += y;
    }
    int tot0 = __shfl_sync(0xffffffffu, x0, 31);
#pragma unroll
    for (int o = 1; o < 32; o <<= 1) {
        int y = __shfl_up_sync(0xffffffffu, x1, o);
        if (lane >= o) x1 += y;
    }
    if (lane < NB) g_boff[lane] = x0 - v0;
    if (32 + lane < NB) g_boff[32 + lane] = tot0 + x1 - v1;
    if (lane == 31) g_row[NN] = tot0 + __shfl_sync(0xffffffffu, x1, 31);
}

// s3: apply block offsets; derive g_pos, g_inv
__global__ void __launch_bounds__(1024) k_scan3() {
    int i = blockIdx.x * 1024 + threadIdx.x;
    if (i < NN) {
        int r = g_row[i] + g_boff[blockIdx.x];
        g_row[i] = r;
        g_pos[i] = r;
        int c = g_cnt[i];
        g_inv[i] = 1.0f / (float)(c > 0 ? c : 1);
    }
}

__global__ void k_fill(const int* __restrict__ eiw) {
    int e = blockIdx.x * blockDim.x + threadIdx.x;
    if (e < EE) {
        int d = edge_at(eiw, EE + e);
        int p = atomicAdd(&g_pos[d], 1);
        g_srcl[p] = edge_at(eiw, e);
    }
}

// ---------------- mean aggregation: one warp per node ----------------
__global__ void k_aggregate(const float* __restrict__ hext, int sel) {
    const float* h = (sel == 1) ? (const float*)g_h1
                   : (sel == 2) ? (const float*)g_h2 : hext;
    int w = (blockIdx.x * blockDim.x + threadIdx.x) >> 5;
    int lane = threadIdx.x & 31;
    if (w >= NN) return;
    int s = g_row[w], e = g_row[w + 1];
    float4 acc = make_float4(0.f, 0.f, 0.f, 0.f);
    for (int i = s; i < e; ++i) {
        int src = g_srcl[i];
        float4 v = *(const float4*)(h + (size_t)src * DD + lane * 4);
        acc.x += v.x; acc.y += v.y; acc.z += v.z; acc.w += v.w;
    }
    float iv = g_inv[w];
    float4 r = make_float4(acc.x * iv, acc.y * iv, acc.z * iv, acc.w * iv);
    *(float4*)(g_agg + (size_t)w * DD + lane * 4) = r;
}

// ---------------- fused SAGE GEMM ----------------
// out[n][o] = relu?( agg[n,:]·Wl[o,:] + Aself[n,:]·Wr[o,:] + b[o] )
// 128-node x 128-out tile, 256 threads, 8x8 register blocking, K tiled by 16.
__global__ void __launch_bounds__(256) k_gemm(
    const float* __restrict__ aself_ext, int asel,
    const float* __restrict__ Wl, const float* __restrict__ Wr,
    const float* __restrict__ bias,
    float* out_ext, int osel, int do_relu)
{
    const float* Aself = (asel == 1) ? (const float*)g_h1
                       : (asel == 2) ? (const float*)g_h2 : aself_ext;
    float* out = (osel == 1) ? (float*)g_h1
               : (osel == 2) ? (float*)g_h2 : out_ext;

    __shared__ float AsT[16 * 128];   // AsT[kk][r]
    __shared__ float Ws[16 * 128];    // Ws[kk][o]

    int t = threadIdx.x;
    int n0 = blockIdx.x * 128;
    int tr = t >> 4, tc = t & 15;
    int r0 = tr * 8, c0 = tc * 8;

    float acc[8][8];
#pragma unroll
    for (int i = 0; i < 8; i++)
#pragma unroll
        for (int j = 0; j < 8; j++) acc[i][j] = 0.f;

#pragma unroll 1
    for (int phase = 0; phase < 2; ++phase) {
        const float* A = phase ? Aself : (const float*)g_agg;
        const float* W = phase ? Wr : Wl;
        const float4* A4 = (const float4*)A;
        const float4* W4 = (const float4*)W;
#pragma unroll 1
        for (int k0 = 0; k0 < 128; k0 += 16) {
            // A tile: 128 rows x 16 k = 512 float4, transposed into AsT[kk][r]
#pragma unroll
            for (int rep = 0; rep < 2; ++rep) {
                int idx = rep * 256 + t;       // 0..511
                int r = idx >> 2, q = idx & 3;
                int n = n0 + r;
                float4 v = make_float4(0.f, 0.f, 0.f, 0.f);
                if (n < NN) v = A4[(size_t)n * 32 + (k0 >> 2) + q];
                int kk = q * 4;
                AsT[(kk + 0) * 128 + r] = v.x;
                AsT[(kk + 1) * 128 + r] = v.y;
                AsT[(kk + 2) * 128 + r] = v.z;
                AsT[(kk + 3) * 128 + r] = v.w;
            }
            // W tile transposed: Ws[kk][o] = W[o][k0+kk]
#pragma unroll
            for (int rep = 0; rep < 2; ++rep) {
                int idx = rep * 256 + t;
                int o = idx >> 2, q = idx & 3;
                float4 v = W4[o * 32 + (k0 >> 2) + q];
                int kk = q * 4;
                Ws[(kk + 0) * 128 + o] = v.x;
                Ws[(kk + 1) * 128 + o] = v.y;
                Ws[(kk + 2) * 128 + o] = v.z;
                Ws[(kk + 3) * 128 + o] = v.w;
            }
            __syncthreads();
#pragma unroll
            for (int kk = 0; kk < 16; ++kk) {
                float4 a0 = *(float4*)&AsT[kk * 128 + r0];
                float4 a1 = *(float4*)&AsT[kk * 128 + r0 + 4];
                float4 w0 = *(float4*)&Ws[kk * 128 + c0];
                float4 w1 = *(float4*)&Ws[kk * 128 + c0 + 4];
                float av[8] = { a0.x, a0.y, a0.z, a0.w, a1.x, a1.y, a1.z, a1.w };
                float wv[8] = { w0.x, w0.y, w0.z, w0.w, w1.x, w1.y, w1.z, w1.w };
#pragma unroll
                for (int i = 0; i < 8; i++)
#pragma unroll
                    for (int j = 0; j < 8; j++)
                        acc[i][j] += av[i] * wv[j];
            }
            __syncthreads();
        }
    }

    float bv[8];
#pragma unroll
    for (int j = 0; j < 8; j++) bv[j] = bias[c0 + j];
#pragma unroll
    for (int i = 0; i < 8; i++) {
        int n = n0 + r0 + i;
        if (n < NN) {
#pragma unroll
            for (int j = 0; j < 8; j++) {
                float v = acc[i][j] + bv[j];
                if (do_relu) v = fmaxf(v, 0.f);
                acc[i][j] = v;
            }
            *(float4*)(out + (size_t)n * DD + c0) =
                make_float4(acc[i][0], acc[i][1], acc[i][2], acc[i][3]);
            *(float4*)(out + (size_t)n * DD + c0 + 4) =
                make_float4(acc[i][4], acc[i][5], acc[i][6], acc[i][7]);
        }
    }
}

// ---------------- decoder: one warp per node ----------------
__global__ void k_decoder(const float* __restrict__ h3, const float* __restrict__ Wo,
                          const float* __restrict__ bo, float* __restrict__ out2) {
    int w = (blockIdx.x * blockDim.x + threadIdx.x) >> 5;
    int lane = threadIdx.x & 31;
    if (w >= NN) return;
    float4 h  = *(const float4*)(h3 + (size_t)w * DD + lane * 4);
    float4 w0 = *(const float4*)(Wo + lane * 4);
    float4 w1 = *(const float4*)(Wo + DD + lane * 4);
    float p0 = h.x * w0.x + h.y * w0.y + h.z * w0.z + h.w * w0.w;
    float p1 = h.x * w1.x + h.y * w1.y + h.z * w1.z + h.w * w1.w;
    for (int off = 16; off; off >>= 1) {
        p0 += __shfl_xor_sync(0xffffffffu, p0, off);
        p1 += __shfl_xor_sync(0xffffffffu, p1, off);
    }
    if (lane == 0) {
        out2[w * 2 + 0] = p0 + bo[0];
        out2[w * 2 + 1] = p1 + bo[1];
    }
}

extern "C" void kernel_launch(void* const* d_in, const int* in_sizes, int n_in,
                              void* d_out, int out_size) {
    const float* x   = (const float*)d_in[0];
    const int*   eiw = (const int*)d_in[1];
    const float* Wl1 = (const float*)d_in[2];
    const float* Wr1 = (const float*)d_in[3];
    const float* b1  = (const float*)d_in[4];
    const float* Wl2 = (const float*)d_in[5];
    const float* Wr2 = (const float*)d_in[6];
    const float* b2  = (const float*)d_in[7];
    const float* Wl3 = (const float*)d_in[8];
    const float* Wr3 = (const float*)d_in[9];
    const float* b3  = (const float*)d_in[10];
    const float* Wo  = (const float*)d_in[11];
    const float* bo  = (const float*)d_in[12];

    float* out  = (float*)d_out;
    float* out2 = out;              // [N, 2]
    float* h3   = out + NN * 2;     // [N, 128]

    // CSR build (edges identical across layers)
    k_detect<<<1, 32>>>(eiw);
    k_zero_cnt<<<(NN + 255) / 256, 256>>>();
    k_count<<<(EE + 255) / 256, 256>>>(eiw);
    k_scan1<<<NB, 1024>>>();
    k_scan2<<<1, 32>>>();
    k_scan3<<<NB, 1024>>>();
    k_fill<<<(EE + 255) / 256, 256>>>(eiw);

    int gemm_blocks = (NN + 127) / 128;
    int warp_blocks = (NN + 7) / 8;

    // layer 1: x -> g_h1 (relu)
    k_aggregate<<<warp_blocks, 256>>>(x, 0);
    k_gemm<<<gemm_blocks, 256>>>(x, 0, Wl1, Wr1, b1, nullptr, 1, 1);

    // layer 2: g_h1 -> g_h2 (relu)
    k_aggregate<<<warp_blocks, 256>>>(nullptr, 1);
    k_gemm<<<gemm_blocks, 256>>>(nullptr, 1, Wl2, Wr2, b2, nullptr, 2, 1);

    // layer 3: g_h2 -> h3 (no relu), straight into d_out
    k_aggregate<<<warp_blocks, 256>>>(nullptr, 2);
    k_gemm<<<gemm_blocks, 256>>>(nullptr, 2, Wl3, Wr3, b3, h3, 0, 0);

    // decoder
    k_decoder<<<warp_blocks, 256>>>(h3, Wo, bo, out2);
}